// round 2
// baseline (speedup 1.0000x reference)
#include <cuda_runtime.h>

#define NNODES 100000
#define DF 256
#define BQ 1024
#define S0 25
#define S1 10
#define N1 (BQ * (1 + S1))   /* 11264 */
#define KDIM 512

// Scratch (allocation-free rule: __device__ globals)
__device__ float g_X1[(size_t)N1 * KDIM];   // concat(self0, agg0)  ~23 MB
__device__ float g_H1[(size_t)N1 * DF];     // layer-1 hidden       ~11.5 MB
__device__ float g_X2[(size_t)BQ * KDIM];   // concat(self1, agg1)  ~2 MB

// ---------------------------------------------------------------------------
// Kernel 1: gather features, build X1 = [self | mean of 25 neighbors]
// grid = N1 blocks, block = 256 threads (one thread per feature column)
// ---------------------------------------------------------------------------
__global__ void gather1_kernel(const float* __restrict__ feat,
                               const int* __restrict__ nodes2,
                               const int* __restrict__ neigh2,
                               const int* __restrict__ neigh1) {
    int r = blockIdx.x;
    int c = threadIdx.x;
    __shared__ int sidx[S0];
    __shared__ int sself;
    if (c < S0) sidx[c] = neigh1[(size_t)r * S0 + c];
    if (c == S0) sself = (r < BQ) ? nodes2[r] : neigh2[r - BQ];
    __syncthreads();

    g_X1[(size_t)r * KDIM + c] = feat[(size_t)sself * DF + c];

    float s = 0.f;
#pragma unroll
    for (int j = 0; j < S0; j++)
        s += feat[(size_t)sidx[j] * DF + c];
    g_X1[(size_t)r * KDIM + DF + c] = s * (1.0f / S0);
}

// ---------------------------------------------------------------------------
// Kernel 3: build X2 = [self1 | mean of 10 layer-1 hiddens] (no index lookup)
// grid = BQ blocks, block = 256 threads
// ---------------------------------------------------------------------------
__global__ void gather2_kernel() {
    int r = blockIdx.x;
    int c = threadIdx.x;
    g_X2[(size_t)r * KDIM + c] = g_H1[(size_t)r * DF + c];
    float s = 0.f;
#pragma unroll
    for (int j = 0; j < S1; j++)
        s += g_H1[(size_t)(BQ + r * S1 + j) * DF + c];
    g_X2[(size_t)r * KDIM + DF + c] = s * (1.0f / S1);
}

// ---------------------------------------------------------------------------
// Fused GEMM + bias + ReLU + row L2-normalize.
// out[m][n] = relu( sum_k X[m][k] * W[n][k] + bias[n] ), then row-normalized.
// N = 256 (full output width per block) so the row-norm stays inside one warp.
// Block: 256 threads = 8 warps. Warp w owns rows [rb + w*RPT, rb + (w+1)*RPT).
// Lane owns columns {lane + 32*i}, i=0..7 (strided -> conflict-free LDS,
// coalesced STG, full-warp shfl reduction for the norm).
// ---------------------------------------------------------------------------
template <int BM>
__global__ void __launch_bounds__(256)
gemm_relu_norm(const float* __restrict__ X,
               const float* __restrict__ W,
               const float* __restrict__ bias,
               float* __restrict__ out) {
    constexpr int RPT = BM / 8;   // rows per warp
    constexpr int KT  = 16;       // K tile

    __shared__ float As[KT][BM + 4];   // +4 pad keeps 16B alignment, kills conflicts
    __shared__ float Ws[KT][DF];

    const int tid  = threadIdx.x;
    const int warp = tid >> 5;
    const int lane = tid & 31;
    const int rb   = blockIdx.x * BM;

    float acc[RPT][8];
#pragma unroll
    for (int r = 0; r < RPT; r++)
#pragma unroll
        for (int i = 0; i < 8; i++) acc[r][i] = 0.f;

    for (int kt = 0; kt < KDIM; kt += KT) {
        // A tile: BM x KT (k fastest in gmem read for coalescing), stored transposed
        for (int idx = tid; idx < BM * KT; idx += 256) {
            int k = idx & (KT - 1);
            int m = idx >> 4;
            As[k][m] = X[(size_t)(rb + m) * KDIM + kt + k];
        }
        // W tile: 256 rows x KT, thread n=tid reads its 16 contiguous k's as float4
        {
            const float4* wp = (const float4*)(W + (size_t)tid * KDIM + kt);
#pragma unroll
            for (int q = 0; q < KT / 4; q++) {
                float4 v = wp[q];
                Ws[q * 4 + 0][tid] = v.x;
                Ws[q * 4 + 1][tid] = v.y;
                Ws[q * 4 + 2][tid] = v.z;
                Ws[q * 4 + 3][tid] = v.w;
            }
        }
        __syncthreads();

#pragma unroll
        for (int k = 0; k < KT; k++) {
            float a[RPT];
#pragma unroll
            for (int r = 0; r < RPT; r++) a[r] = As[k][warp * RPT + r];
            float b[8];
#pragma unroll
            for (int i = 0; i < 8; i++) b[i] = Ws[k][lane + 32 * i];
#pragma unroll
            for (int r = 0; r < RPT; r++)
#pragma unroll
                for (int i = 0; i < 8; i++)
                    acc[r][i] += a[r] * b[i];
        }
        __syncthreads();
    }

    // Epilogue: bias + relu + per-row L2 norm (entirely within the warp) + store
#pragma unroll
    for (int r = 0; r < RPT; r++) {
        float ss = 0.f;
#pragma unroll
        for (int i = 0; i < 8; i++) {
            float v = acc[r][i] + bias[lane + 32 * i];
            v = fmaxf(v, 0.f);
            acc[r][i] = v;
            ss += v * v;
        }
#pragma unroll
        for (int o = 16; o > 0; o >>= 1)
            ss += __shfl_xor_sync(0xffffffffu, ss, o);
        float inv = (ss > 0.f) ? rsqrtf(ss) : 1.0f;
        int row = rb + warp * RPT + r;
#pragma unroll
        for (int i = 0; i < 8; i++)
            out[(size_t)row * DF + lane + 32 * i] = acc[r][i] * inv;
    }
}

// ---------------------------------------------------------------------------
extern "C" void kernel_launch(void* const* d_in, const int* in_sizes, int n_in,
                              void* d_out, int out_size) {
    const float* features = (const float*)d_in[0];
    const float* W0       = (const float*)d_in[1];
    const float* b0       = (const float*)d_in[2];
    const float* W1       = (const float*)d_in[3];
    const float* b1       = (const float*)d_in[4];
    const int*   nodes2   = (const int*)d_in[5];
    const int*   neigh2   = (const int*)d_in[6];
    const int*   neigh1   = (const int*)d_in[7];
    float*       outp     = (float*)d_out;

    float *x1, *h1, *x2;
    cudaGetSymbolAddress((void**)&x1, g_X1);
    cudaGetSymbolAddress((void**)&h1, g_H1);
    cudaGetSymbolAddress((void**)&x2, g_X2);

    gather1_kernel<<<N1, 256>>>(features, nodes2, neigh2, neigh1);
    gemm_relu_norm<64><<<N1 / 64, 256>>>(x1, W0, b0, h1);
    gather2_kernel<<<BQ, 256>>>();
    gemm_relu_norm<16><<<BQ / 16, 256>>>(x2, W1, b1, outp);
}

// round 4
// speedup vs baseline: 2.6767x; 2.6767x over previous
#include <cuda_runtime.h>
#include <cstdint>

#define NNODES 100000
#define DF 256
#define BQ 1024
#define S0 25
#define S1 10
#define N1 (BQ * (1 + S1))   /* 11264 */
#define KDIM 512
#define BK 32
#define NCH (KDIM / BK)      /* 16 */
#define ASTR 36              /* BK + 4 : conflict-free frag loads */
#define CSTR 264             /* 256 + 8 */

// ---------------- scratch (__device__ globals; no allocs allowed) ----------
__device__ float g_X1[(size_t)N1 * KDIM];
__device__ float g_H1[(size_t)N1 * DF];
__device__ float g_X2[(size_t)BQ * KDIM];

// ---------------- small PTX helpers ---------------------------------------
__device__ __forceinline__ uint32_t smem_u32(const void* p) {
    uint32_t a;
    asm("{ .reg .u64 t; cvta.to.shared.u64 t, %1; cvt.u32.u64 %0, t; }" : "=r"(a) : "l"(p));
    return a;
}
__device__ __forceinline__ void cpa16(uint32_t dst, const void* src) {
    asm volatile("cp.async.cg.shared.global [%0], [%1], 16;" :: "r"(dst), "l"(src));
}
#define CP_COMMIT() asm volatile("cp.async.commit_group;" ::: "memory")
#define CP_WAIT(n)  asm volatile("cp.async.wait_group %0;" :: "n"(n) : "memory")

__device__ __forceinline__ uint32_t f2tf32(float f) {
    uint32_t u;
    asm("cvt.rna.tf32.f32 %0, %1;" : "=r"(u) : "f"(f));
    return u;
}
__device__ __forceinline__ void mma_tf32(float* d, const uint32_t* a, const uint32_t* b) {
    asm volatile(
        "mma.sync.aligned.m16n8k8.row.col.f32.tf32.tf32.f32 "
        "{%0,%1,%2,%3},{%4,%5,%6,%7},{%8,%9},{%0,%1,%2,%3};"
        : "+f"(d[0]), "+f"(d[1]), "+f"(d[2]), "+f"(d[3])
        : "r"(a[0]), "r"(a[1]), "r"(a[2]), "r"(a[3]), "r"(b[0]), "r"(b[1]));
}

// ---------------------------------------------------------------------------
// Gather 1: X1 = [feat[self] | mean_{25} feat[neigh]]   (float4 throughout)
// ---------------------------------------------------------------------------
__global__ void __launch_bounds__(256) gather1_kernel(
    const float4* __restrict__ F, const int* __restrict__ nodes2,
    const int* __restrict__ neigh2, const int* __restrict__ neigh1) {
    int g = threadIdx.x >> 6, c = threadIdx.x & 63;
    int r = blockIdx.x * 4 + g;
    __shared__ int sidx[4][S0 + 1];
    if (c < S0) sidx[g][c] = neigh1[(size_t)r * S0 + c];
    else if (c == S0) sidx[g][S0] = (r < BQ) ? nodes2[r] : neigh2[r - BQ];
    __syncthreads();

    float4* X1v = (float4*)g_X1;
    X1v[(size_t)r * 128 + c] = F[(size_t)sidx[g][S0] * 64 + c];

    float4 s = make_float4(0.f, 0.f, 0.f, 0.f);
#pragma unroll
    for (int j = 0; j < S0; j++) {
        float4 v = F[(size_t)sidx[g][j] * 64 + c];
        s.x += v.x; s.y += v.y; s.z += v.z; s.w += v.w;
    }
    const float is = 1.0f / S0;
    s.x *= is; s.y *= is; s.z *= is; s.w *= is;
    X1v[(size_t)r * 128 + 64 + c] = s;
}

// ---------------------------------------------------------------------------
// Gather 2: X2 = [H1[r] | mean_{10} H1[BQ + r*10 + j]]
// ---------------------------------------------------------------------------
__global__ void __launch_bounds__(64) gather2_kernel() {
    int r = blockIdx.x, c = threadIdx.x;
    const float4* H = (const float4*)g_H1;
    float4* X2v = (float4*)g_X2;
    X2v[(size_t)r * 128 + c] = H[(size_t)r * 64 + c];
    float4 s = make_float4(0.f, 0.f, 0.f, 0.f);
#pragma unroll
    for (int j = 0; j < S1; j++) {
        float4 v = H[(size_t)(BQ + r * S1 + j) * 64 + c];
        s.x += v.x; s.y += v.y; s.z += v.z; s.w += v.w;
    }
    const float is = 1.0f / S1;
    s.x *= is; s.y *= is; s.z *= is; s.w *= is;
    X2v[(size_t)r * 128 + 64 + c] = s;
}

// ---------------------------------------------------------------------------
// tf32 mma.sync GEMM + bias + ReLU + row-L2-norm.
// out[m][n] = l2norm_row( relu( sum_k X[m][k]*W[n][k] + bias[n] ) )
// CTA covers BM rows x full N=256. K pipelined via cp.async, 2 stages, BK=32.
// Warp grid WARPS_M x WARPS_N; warp tile (BM/WARPS_M) x (256/WARPS_N).
// A/B smem [row][k] stride 36 -> conflict-free m16n8k8 fragment loads.
// ---------------------------------------------------------------------------
template <int BM, int THREADS, int WARPS_M, int WARPS_N>
__global__ void __launch_bounds__(THREADS, 1)
gemm_mma(const float* __restrict__ X, const float* __restrict__ W,
         const float* __restrict__ bias, float* __restrict__ out) {
    constexpr int BN = 256;
    constexpr int WM = BM / WARPS_M;
    constexpr int WN = BN / WARPS_N;
    constexpr int MT = WM / 16;
    constexpr int NT = WN / 8;
    constexpr int TPR = THREADS / BM;   // threads per row (norm pass)
    constexpr int CP  = BN / TPR;       // cols per thread (norm pass)

    extern __shared__ float sm[];
    float* As = sm;                       // [2][BM][ASTR]
    float* Bs = sm + 2 * BM * ASTR;       // [2][BN][ASTR]
    float* Cs = sm;                       // [BM][CSTR]  (reused after compute)

    const int tid  = threadIdx.x;
    const int wid  = tid >> 5;
    const int lane = tid & 31;
    const int wrow = wid / WARPS_N;
    const int wcol = wid % WARPS_N;
    const int rb   = blockIdx.x * BM;
    const int lq   = lane >> 2;   // 0..7
    const int lr   = lane & 3;    // 0..3

    const uint32_t as_b = smem_u32(As);
    const uint32_t bs_b = smem_u32(Bs);

    float acc[MT][NT][4];
#pragma unroll
    for (int i = 0; i < MT; i++)
#pragma unroll
        for (int j = 0; j < NT; j++)
#pragma unroll
            for (int q = 0; q < 4; q++) acc[i][j][q] = 0.f;

    auto stage = [&](int ch, int buf) {
        const float* xb = X + (size_t)rb * KDIM + ch * BK;
        const float* wb = W + ch * BK;
#pragma unroll
        for (int i = tid; i < BM * 8; i += THREADS) {
            int r = i >> 3, s = i & 7;
            cpa16(as_b + ((buf * BM + r) * ASTR + s * 4) * 4, xb + (size_t)r * KDIM + s * 4);
        }
#pragma unroll
        for (int i = tid; i < BN * 8; i += THREADS) {
            int n = i >> 3, s = i & 7;
            cpa16(bs_b + ((buf * BN + n) * ASTR + s * 4) * 4, wb + (size_t)n * KDIM + s * 4);
        }
    };

    auto compute = [&](int buf) {
#pragma unroll
        for (int ks = 0; ks < 4; ks++) {
            const int k0 = ks * 8;
            uint32_t af[MT][4];
#pragma unroll
            for (int mt = 0; mt < MT; mt++) {
                const float* ap = As + (size_t)(buf * BM + wrow * WM + mt * 16 + lq) * ASTR + k0 + lr;
                af[mt][0] = f2tf32(ap[0]);
                af[mt][1] = f2tf32(ap[8 * ASTR]);
                af[mt][2] = f2tf32(ap[4]);
                af[mt][3] = f2tf32(ap[8 * ASTR + 4]);
            }
            uint32_t bf[NT][2];
#pragma unroll
            for (int nt = 0; nt < NT; nt++) {
                const float* bp = Bs + (size_t)(buf * BN + wcol * WN + nt * 8 + lq) * ASTR + k0 + lr;
                bf[nt][0] = f2tf32(bp[0]);
                bf[nt][1] = f2tf32(bp[4]);
            }
#pragma unroll
            for (int mt = 0; mt < MT; mt++)
#pragma unroll
                for (int nt = 0; nt < NT; nt++)
                    mma_tf32(acc[mt][nt], af[mt], bf[nt]);
        }
    };

    stage(0, 0);
    CP_COMMIT();
    for (int ch = 0; ch < NCH; ch++) {
        if (ch + 1 < NCH) {
            stage(ch + 1, (ch + 1) & 1);
            CP_COMMIT();
            CP_WAIT(1);
        } else {
            CP_WAIT(0);
        }
        __syncthreads();
        compute(ch & 1);
        __syncthreads();
    }

    // ---- epilogue: accums -> Cs with bias+relu ----
#pragma unroll
    for (int mt = 0; mt < MT; mt++) {
        const int row = wrow * WM + mt * 16 + lq;
#pragma unroll
        for (int nt = 0; nt < NT; nt++) {
            const int col = wcol * WN + nt * 8 + 2 * lr;
            const float b0 = __ldg(&bias[col]);
            const float b1 = __ldg(&bias[col + 1]);
            Cs[(size_t)row * CSTR + col]           = fmaxf(acc[mt][nt][0] + b0, 0.f);
            Cs[(size_t)row * CSTR + col + 1]       = fmaxf(acc[mt][nt][1] + b1, 0.f);
            Cs[(size_t)(row + 8) * CSTR + col]     = fmaxf(acc[mt][nt][2] + b0, 0.f);
            Cs[(size_t)(row + 8) * CSTR + col + 1] = fmaxf(acc[mt][nt][3] + b1, 0.f);
        }
    }
    __syncthreads();

    // ---- row L2 norm: TPR threads per row, shfl reduce, float4 STG ----
    {
        const int row  = tid / TPR;
        const int part = tid % TPR;
        const float* src = Cs + (size_t)row * CSTR + part * CP;
        float ssq = 0.f;
#pragma unroll
        for (int j = 0; j < CP / 4; j++) {
            float4 v = ((const float4*)src)[j];
            ssq += v.x * v.x + v.y * v.y + v.z * v.z + v.w * v.w;
        }
#pragma unroll
        for (int o = TPR / 2; o > 0; o >>= 1)
            ssq += __shfl_xor_sync(0xffffffffu, ssq, o);
        const float inv = (ssq > 0.f) ? rsqrtf(ssq) : 1.0f;
        float4* dst = (float4*)(out + (size_t)(rb + row) * BN + part * CP);
#pragma unroll
        for (int j = 0; j < CP / 4; j++) {
            float4 v = ((const float4*)src)[j];
            v.x *= inv; v.y *= inv; v.z *= inv; v.w *= inv;
            dst[j] = v;
        }
    }
}

// smem sizes (bytes)
#define SM_STAGE(BM) (2 * ((BM) + 256) * ASTR * 4)
#define SM_EPI(BM)   ((BM) * CSTR * 4)
#define SM_SZ(BM)    (SM_STAGE(BM) > SM_EPI(BM) ? SM_STAGE(BM) : SM_EPI(BM))

// ---------------------------------------------------------------------------
extern "C" void kernel_launch(void* const* d_in, const int* in_sizes, int n_in,
                              void* d_out, int out_size) {
    const float* features = (const float*)d_in[0];
    const float* W0       = (const float*)d_in[1];
    const float* b0       = (const float*)d_in[2];
    const float* W1       = (const float*)d_in[3];
    const float* b1       = (const float*)d_in[4];
    const int*   nodes2   = (const int*)d_in[5];
    const int*   neigh2   = (const int*)d_in[6];
    const int*   neigh1   = (const int*)d_in[7];
    float*       outp     = (float*)d_out;

    float *x1, *h1, *x2;
    cudaGetSymbolAddress((void**)&x1, g_X1);
    cudaGetSymbolAddress((void**)&h1, g_H1);
    cudaGetSymbolAddress((void**)&x2, g_X2);

    constexpr int SM1 = SM_SZ(128);   // 135168
    constexpr int SM2 = SM_SZ(32);    //  82944
    static bool attr_done = false;
    if (!attr_done) {
        cudaFuncSetAttribute((const void*)gemm_mma<128, 512, 4, 4>,
                             cudaFuncAttributeMaxDynamicSharedMemorySize, SM1);
        cudaFuncSetAttribute((const void*)gemm_mma<32, 256, 2, 4>,
                             cudaFuncAttributeMaxDynamicSharedMemorySize, SM2);
        attr_done = true;
    }

    gather1_kernel<<<N1 / 4, 256>>>((const float4*)features, nodes2, neigh2, neigh1);
    gemm_mma<128, 512, 4, 4><<<N1 / 128, 512, SM1>>>(x1, W0, b0, h1);
    gather2_kernel<<<BQ, 64>>>();
    gemm_mma<32, 256, 2, 4><<<BQ / 32, 256, SM2>>>(x2, W1, b1, outp);
}

// round 5
// speedup vs baseline: 3.1989x; 1.1951x over previous
#include <cuda_runtime.h>
#include <cstdint>

#define NNODES 100000
#define DF 256
#define BQ 1024
#define S0 25
#define S1 10
#define N1 (BQ * (1 + S1))   /* 11264 */
#define KDIM 512
#define BK 32
#define NCH (KDIM / BK)      /* 16 */
#define ASTR 36              /* BK + 4 : conflict-free frag loads */

// ---------------- scratch (__device__ globals; no allocs allowed) ----------
__device__ float g_X1[(size_t)N1 * KDIM];
__device__ float g_H1[(size_t)N1 * DF];
__device__ float g_X2[(size_t)BQ * KDIM];
__device__ float g_W0r[(size_t)DF * KDIM];
__device__ float g_W1r[(size_t)DF * KDIM];
__device__ float g_P[4][(size_t)BQ * DF];     // split-K partials for layer 2

// ---------------- small PTX helpers ---------------------------------------
__device__ __forceinline__ uint32_t smem_u32(const void* p) {
    uint32_t a;
    asm("{ .reg .u64 t; cvta.to.shared.u64 t, %1; cvt.u32.u64 %0, t; }" : "=r"(a) : "l"(p));
    return a;
}
__device__ __forceinline__ void cpa16(uint32_t dst, const void* src) {
    asm volatile("cp.async.cg.shared.global [%0], [%1], 16;" :: "r"(dst), "l"(src));
}
#define CP_COMMIT() asm volatile("cp.async.commit_group;" ::: "memory")
#define CP_WAIT(n)  asm volatile("cp.async.wait_group %0;" :: "n"(n) : "memory")

__device__ __forceinline__ float tf32r(float f) {
    uint32_t u;
    asm("cvt.rna.tf32.f32 %0, %1;" : "=r"(u) : "f"(f));
    return __uint_as_float(u);
}
__device__ __forceinline__ float4 tf32r4(float4 v) {
    return make_float4(tf32r(v.x), tf32r(v.y), tf32r(v.z), tf32r(v.w));
}
__device__ __forceinline__ void mma_tf32(float* d, const uint32_t* a, const uint32_t* b) {
    asm volatile(
        "mma.sync.aligned.m16n8k8.row.col.f32.tf32.tf32.f32 "
        "{%0,%1,%2,%3},{%4,%5,%6,%7},{%8,%9},{%0,%1,%2,%3};"
        : "+f"(d[0]), "+f"(d[1]), "+f"(d[2]), "+f"(d[3])
        : "r"(a[0]), "r"(a[1]), "r"(a[2]), "r"(a[3]), "r"(b[0]), "r"(b[1]));
}

// ---------------------------------------------------------------------------
// Prep: round both weight matrices to tf32 once (numerics == cvt in mainloop)
// ---------------------------------------------------------------------------
__global__ void __launch_bounds__(256) prep_w(const float* __restrict__ W0,
                                              const float* __restrict__ W1) {
    int i = blockIdx.x * 256 + threadIdx.x;   // grid 512 -> 131072 = DF*KDIM
    g_W0r[i] = tf32r(W0[i]);
    g_W1r[i] = tf32r(W1[i]);
}

// ---------------------------------------------------------------------------
// Gather 1: X1 = tf32round([feat[self] | mean_{25} feat[neigh]])
// ---------------------------------------------------------------------------
__global__ void __launch_bounds__(256) gather1_kernel(
    const float4* __restrict__ F, const int* __restrict__ nodes2,
    const int* __restrict__ neigh2, const int* __restrict__ neigh1) {
    int g = threadIdx.x >> 6, c = threadIdx.x & 63;
    int r = blockIdx.x * 4 + g;
    __shared__ int sidx[4][S0 + 1];
    if (c < S0) sidx[g][c] = neigh1[(size_t)r * S0 + c];
    else if (c == S0) sidx[g][S0] = (r < BQ) ? nodes2[r] : neigh2[r - BQ];
    __syncthreads();

    float4* X1v = (float4*)g_X1;
    X1v[(size_t)r * 128 + c] = tf32r4(F[(size_t)sidx[g][S0] * 64 + c]);

    float4 s = make_float4(0.f, 0.f, 0.f, 0.f);
#pragma unroll
    for (int j = 0; j < S0; j++) {
        float4 v = F[(size_t)sidx[g][j] * 64 + c];
        s.x += v.x; s.y += v.y; s.z += v.z; s.w += v.w;
    }
    const float is = 1.0f / S0;
    s.x *= is; s.y *= is; s.z *= is; s.w *= is;
    X1v[(size_t)r * 128 + 64 + c] = tf32r4(s);
}

// ---------------------------------------------------------------------------
// Gather 2: X2 = tf32round([H1[r] | mean_{10} H1[...]])
// ---------------------------------------------------------------------------
__global__ void __launch_bounds__(64) gather2_kernel() {
    int r = blockIdx.x, c = threadIdx.x;
    const float4* H = (const float4*)g_H1;
    float4* X2v = (float4*)g_X2;
    X2v[(size_t)r * 128 + c] = tf32r4(H[(size_t)r * 64 + c]);
    float4 s = make_float4(0.f, 0.f, 0.f, 0.f);
#pragma unroll
    for (int j = 0; j < S1; j++) {
        float4 v = H[(size_t)(BQ + r * S1 + j) * 64 + c];
        s.x += v.x; s.y += v.y; s.z += v.z; s.w += v.w;
    }
    const float is = 1.0f / S1;
    s.x *= is; s.y *= is; s.z *= is; s.w *= is;
    X2v[(size_t)r * 128 + 64 + c] = tf32r4(s);
}

// ---------------------------------------------------------------------------
// GEMM1: 128x256x512 per CTA, tf32 mma.sync, inputs pre-rounded (no cvt in
// loop). 256 threads, 2x4 warps, warp tile 64x64 (MT=4, NT=8).
// Epilogue: bias+ReLU+row-L2-norm straight from accum regs; cross-warp ssq
// via tiny smem exchange.
// ---------------------------------------------------------------------------
__global__ void __launch_bounds__(256, 1)
gemm1_kernel(const float* __restrict__ X, const float* __restrict__ W,
             const float* __restrict__ bias, float* __restrict__ out) {
    constexpr int BM = 128, BN = 256, MT = 4, NT = 8;

    extern __shared__ float sm[];
    float* As = sm;                    // [2][BM][ASTR]
    float* Bs = sm + 2 * BM * ASTR;    // [2][BN][ASTR]
    float* ssq_s = sm;                 // reused post-compute: [128][4]
    float* inv_s = sm + 512;           // [128]

    const int tid  = threadIdx.x;
    const int wid  = tid >> 5;
    const int lane = tid & 31;
    const int wrow = wid >> 2;         // 0..1
    const int wcol = wid & 3;          // 0..3
    const int rb   = blockIdx.x * BM;
    const int lq   = lane >> 2;
    const int lr   = lane & 3;

    const uint32_t as_b = smem_u32(As);
    const uint32_t bs_b = smem_u32(Bs);

    float acc[MT][NT][4];
#pragma unroll
    for (int i = 0; i < MT; i++)
#pragma unroll
        for (int j = 0; j < NT; j++)
#pragma unroll
            for (int q = 0; q < 4; q++) acc[i][j][q] = 0.f;

    auto stage = [&](int ch, int buf) {
        const float* xb = X + (size_t)rb * KDIM + ch * BK;
        const float* wb = W + ch * BK;
#pragma unroll
        for (int i = tid; i < BM * 8; i += 256) {
            int r = i >> 3, s = i & 7;
            cpa16(as_b + ((buf * BM + r) * ASTR + s * 4) * 4, xb + (size_t)r * KDIM + s * 4);
        }
#pragma unroll
        for (int i = tid; i < BN * 8; i += 256) {
            int n = i >> 3, s = i & 7;
            cpa16(bs_b + ((buf * BN + n) * ASTR + s * 4) * 4, wb + (size_t)n * KDIM + s * 4);
        }
    };

    auto compute = [&](int buf) {
#pragma unroll
        for (int ks = 0; ks < 4; ks++) {
            const int k0 = ks * 8;
            uint32_t af[MT][4];
#pragma unroll
            for (int mt = 0; mt < MT; mt++) {
                const uint32_t* ap = (const uint32_t*)(As
                    + (size_t)(buf * BM + wrow * 64 + mt * 16 + lq) * ASTR + k0 + lr);
                af[mt][0] = ap[0];
                af[mt][1] = ap[8 * ASTR];
                af[mt][2] = ap[4];
                af[mt][3] = ap[8 * ASTR + 4];
            }
            uint32_t bf[NT][2];
#pragma unroll
            for (int nt = 0; nt < NT; nt++) {
                const uint32_t* bp = (const uint32_t*)(Bs
                    + (size_t)(buf * BN + wcol * 64 + nt * 8 + lq) * ASTR + k0 + lr);
                bf[nt][0] = bp[0];
                bf[nt][1] = bp[4];
            }
#pragma unroll
            for (int mt = 0; mt < MT; mt++)
#pragma unroll
                for (int nt = 0; nt < NT; nt++)
                    mma_tf32(acc[mt][nt], af[mt], bf[nt]);
        }
    };

    stage(0, 0);
    CP_COMMIT();
    for (int ch = 0; ch < NCH; ch++) {
        if (ch + 1 < NCH) {
            stage(ch + 1, (ch + 1) & 1);
            CP_COMMIT();
            CP_WAIT(1);
        } else {
            CP_WAIT(0);
        }
        __syncthreads();
        compute(ch & 1);
        __syncthreads();
    }

    // ---- epilogue: bias + relu into regs, ssq partials ----
#pragma unroll
    for (int mt = 0; mt < MT; mt++) {
        float s0 = 0.f, s1 = 0.f;
#pragma unroll
        for (int nt = 0; nt < NT; nt++) {
            const int col = wcol * 64 + nt * 8 + 2 * lr;
            const float b0 = __ldg(&bias[col]);
            const float b1 = __ldg(&bias[col + 1]);
            float v0 = fmaxf(acc[mt][nt][0] + b0, 0.f);
            float v1 = fmaxf(acc[mt][nt][1] + b1, 0.f);
            float v2 = fmaxf(acc[mt][nt][2] + b0, 0.f);
            float v3 = fmaxf(acc[mt][nt][3] + b1, 0.f);
            acc[mt][nt][0] = v0; acc[mt][nt][1] = v1;
            acc[mt][nt][2] = v2; acc[mt][nt][3] = v3;
            s0 += v0 * v0 + v1 * v1;
            s1 += v2 * v2 + v3 * v3;
        }
        // reduce over the 4 lr lanes (same row group)
        s0 += __shfl_xor_sync(0xffffffffu, s0, 1);
        s0 += __shfl_xor_sync(0xffffffffu, s0, 2);
        s1 += __shfl_xor_sync(0xffffffffu, s1, 1);
        s1 += __shfl_xor_sync(0xffffffffu, s1, 2);
        if (lr == 0) {
            ssq_s[(wrow * 64 + mt * 16 + lq) * 4 + wcol] = s0;
            ssq_s[(wrow * 64 + mt * 16 + lq + 8) * 4 + wcol] = s1;
        }
    }
    __syncthreads();
    if (tid < 128) {
        float t = ssq_s[tid * 4] + ssq_s[tid * 4 + 1] + ssq_s[tid * 4 + 2] + ssq_s[tid * 4 + 3];
        inv_s[tid] = (t > 0.f) ? rsqrtf(t) : 1.0f;
    }
    __syncthreads();

#pragma unroll
    for (int mt = 0; mt < MT; mt++) {
        const int r0 = wrow * 64 + mt * 16 + lq;
        const float i0 = inv_s[r0], i1 = inv_s[r0 + 8];
#pragma unroll
        for (int nt = 0; nt < NT; nt++) {
            const int col = wcol * 64 + nt * 8 + 2 * lr;
            float2 v0 = make_float2(acc[mt][nt][0] * i0, acc[mt][nt][1] * i0);
            float2 v1 = make_float2(acc[mt][nt][2] * i1, acc[mt][nt][3] * i1);
            *(float2*)(out + (size_t)(rb + r0) * DF + col)     = v0;
            *(float2*)(out + (size_t)(rb + r0 + 8) * DF + col) = v1;
        }
    }
}

// ---------------------------------------------------------------------------
// GEMM2 split-K: each CTA does 32 rows x 256 cols over K slice of 128.
// 256 threads, 2x4 warps, MT=1, NT=8. Raw partials -> g_P[split].
// ---------------------------------------------------------------------------
__global__ void __launch_bounds__(256, 1)
gemm2_splitk(const float* __restrict__ X, const float* __restrict__ W) {
    constexpr int BM = 32, BN = 256, NT = 8;

    extern __shared__ float sm[];
    float* As = sm;                    // [2][BM][ASTR]
    float* Bs = sm + 2 * BM * ASTR;    // [2][BN][ASTR]

    const int tid  = threadIdx.x;
    const int wid  = tid >> 5;
    const int lane = tid & 31;
    const int wrow = wid >> 2;
    const int wcol = wid & 3;
    const int rb   = blockIdx.x * BM;
    const int split = blockIdx.y;
    const int kbase = split * 128;
    const int lq   = lane >> 2;
    const int lr   = lane & 3;

    const uint32_t as_b = smem_u32(As);
    const uint32_t bs_b = smem_u32(Bs);

    float acc[NT][4];
#pragma unroll
    for (int j = 0; j < NT; j++)
#pragma unroll
        for (int q = 0; q < 4; q++) acc[j][q] = 0.f;

    auto stage = [&](int ch, int buf) {
        const float* xb = X + (size_t)rb * KDIM + kbase + ch * BK;
        const float* wb = W + kbase + ch * BK;
#pragma unroll
        for (int i = tid; i < BM * 8; i += 256) {
            int r = i >> 3, s = i & 7;
            cpa16(as_b + ((buf * BM + r) * ASTR + s * 4) * 4, xb + (size_t)r * KDIM + s * 4);
        }
#pragma unroll
        for (int i = tid; i < BN * 8; i += 256) {
            int n = i >> 3, s = i & 7;
            cpa16(bs_b + ((buf * BN + n) * ASTR + s * 4) * 4, wb + (size_t)n * KDIM + s * 4);
        }
    };

    auto compute = [&](int buf) {
#pragma unroll
        for (int ks = 0; ks < 4; ks++) {
            const int k0 = ks * 8;
            uint32_t af[4];
            {
                const uint32_t* ap = (const uint32_t*)(As
                    + (size_t)(buf * BM + wrow * 16 + lq) * ASTR + k0 + lr);
                af[0] = ap[0];
                af[1] = ap[8 * ASTR];
                af[2] = ap[4];
                af[3] = ap[8 * ASTR + 4];
            }
            uint32_t bf[NT][2];
#pragma unroll
            for (int nt = 0; nt < NT; nt++) {
                const uint32_t* bp = (const uint32_t*)(Bs
                    + (size_t)(buf * BN + wcol * 64 + nt * 8 + lq) * ASTR + k0 + lr);
                bf[nt][0] = bp[0];
                bf[nt][1] = bp[4];
            }
#pragma unroll
            for (int nt = 0; nt < NT; nt++)
                mma_tf32(acc[nt], af, bf[nt]);
        }
    };

    stage(0, 0);
    CP_COMMIT();
    for (int ch = 0; ch < 4; ch++) {
        if (ch + 1 < 4) {
            stage(ch + 1, (ch + 1) & 1);
            CP_COMMIT();
            CP_WAIT(1);
        } else {
            CP_WAIT(0);
        }
        __syncthreads();
        compute(ch & 1);
        __syncthreads();
    }

    float* P = g_P[split];
    const int r0 = wrow * 16 + lq;
#pragma unroll
    for (int nt = 0; nt < NT; nt++) {
        const int col = wcol * 64 + nt * 8 + 2 * lr;
        *(float2*)(P + (size_t)(rb + r0) * DF + col)     = make_float2(acc[nt][0], acc[nt][1]);
        *(float2*)(P + (size_t)(rb + r0 + 8) * DF + col) = make_float2(acc[nt][2], acc[nt][3]);
    }
}

// ---------------------------------------------------------------------------
// Combine: sum 4 partials + bias + relu + L2 norm -> final output.
// One warp per row, 8 rows per 256-thread block.
// ---------------------------------------------------------------------------
__global__ void __launch_bounds__(256) combine_kernel(const float* __restrict__ bias,
                                                      float* __restrict__ out) {
    const int wid = threadIdx.x >> 5, lane = threadIdx.x & 31;
    const int row = blockIdx.x * 8 + wid;

    const float4* P0 = (const float4*)(g_P[0] + (size_t)row * DF);
    const float4* P1 = (const float4*)(g_P[1] + (size_t)row * DF);
    const float4* P2 = (const float4*)(g_P[2] + (size_t)row * DF);
    const float4* P3 = (const float4*)(g_P[3] + (size_t)row * DF);
    const float4* Bv = (const float4*)bias;

    float4 v[2];
    float ssq = 0.f;
#pragma unroll
    for (int t = 0; t < 2; t++) {
        const int idx = lane + t * 32;
        float4 a = P0[idx], b = P1[idx], c = P2[idx], d = P3[idx], e = Bv[idx];
        float4 r;
        r.x = fmaxf(a.x + b.x + c.x + d.x + e.x, 0.f);
        r.y = fmaxf(a.y + b.y + c.y + d.y + e.y, 0.f);
        r.z = fmaxf(a.z + b.z + c.z + d.z + e.z, 0.f);
        r.w = fmaxf(a.w + b.w + c.w + d.w + e.w, 0.f);
        ssq += r.x * r.x + r.y * r.y + r.z * r.z + r.w * r.w;
        v[t] = r;
    }
#pragma unroll
    for (int o = 16; o > 0; o >>= 1)
        ssq += __shfl_xor_sync(0xffffffffu, ssq, o);
    const float inv = (ssq > 0.f) ? rsqrtf(ssq) : 1.0f;

    float4* dst = (float4*)(out + (size_t)row * DF);
#pragma unroll
    for (int t = 0; t < 2; t++) {
        float4 r = v[t];
        r.x *= inv; r.y *= inv; r.z *= inv; r.w *= inv;
        dst[lane + t * 32] = r;
    }
}

// ---------------------------------------------------------------------------
extern "C" void kernel_launch(void* const* d_in, const int* in_sizes, int n_in,
                              void* d_out, int out_size) {
    const float* features = (const float*)d_in[0];
    const float* W0       = (const float*)d_in[1];
    const float* b0       = (const float*)d_in[2];
    const float* W1       = (const float*)d_in[3];
    const float* b1       = (const float*)d_in[4];
    const int*   nodes2   = (const int*)d_in[5];
    const int*   neigh2   = (const int*)d_in[6];
    const int*   neigh1   = (const int*)d_in[7];
    float*       outp     = (float*)d_out;

    float *x1, *h1, *x2, *w0r, *w1r;
    cudaGetSymbolAddress((void**)&x1, g_X1);
    cudaGetSymbolAddress((void**)&h1, g_H1);
    cudaGetSymbolAddress((void**)&x2, g_X2);
    cudaGetSymbolAddress((void**)&w0r, g_W0r);
    cudaGetSymbolAddress((void**)&w1r, g_W1r);

    constexpr int SM1 = 2 * (128 + 256) * ASTR * 4;   // 110592
    constexpr int SM2 = 2 * (32 + 256) * ASTR * 4;    //  82944
    static bool attr_done = false;
    if (!attr_done) {
        cudaFuncSetAttribute((const void*)gemm1_kernel,
                             cudaFuncAttributeMaxDynamicSharedMemorySize, SM1);
        cudaFuncSetAttribute((const void*)gemm2_splitk,
                             cudaFuncAttributeMaxDynamicSharedMemorySize, SM2);
        attr_done = true;
    }

    prep_w<<<512, 256>>>(W0, W1);
    gather1_kernel<<<N1 / 4, 256>>>((const float4*)features, nodes2, neigh2, neigh1);
    gemm1_kernel<<<N1 / 128, 256, SM1>>>(x1, w0r, b0, h1);
    gather2_kernel<<<BQ, 64>>>();
    gemm2_splitk<<<dim3(BQ / 32, 4), 256, SM2>>>(x2, w1r);
    combine_kernel<<<BQ / 8, 256>>>(b1, outp);
}